// round 14
// baseline (speedup 1.0000x reference)
#include <cuda_runtime.h>
#include <math.h>

#define N_NODES 50000
#define N_EDGES 800000
#define HID 128
#define ANF 32
#define EPSV 1e-12f

typedef unsigned long long ull;

__device__ float g_hA[N_NODES * HID];
__device__ float g_hB[N_NODES * HID];
__device__ float g_sum[N_NODES * HID];
__device__ float g_cnt[N_NODES];

__device__ __forceinline__ ull pack2(float x, float y) {
    ull r;
    asm("mov.b64 %0,{%1,%2};" : "=l"(r) : "r"(__float_as_uint(x)), "r"(__float_as_uint(y)));
    return r;
}
__device__ __forceinline__ ull dup2(float x) {
    ull r;
    asm("mov.b64 %0,{%1,%1};" : "=l"(r) : "r"(__float_as_uint(x)));
    return r;
}
__device__ __forceinline__ float2 unpack2(ull v) {
    unsigned a, b;
    asm("mov.b64 {%0,%1},%2;" : "=r"(a), "=r"(b) : "l"(v));
    return make_float2(__uint_as_float(a), __uint_as_float(b));
}
__device__ __forceinline__ ull fma2(ull a, ull b, ull c) {
    ull d;
    asm("fma.rn.f32x2 %0,%1,%2,%3;" : "=l"(d) : "l"(a), "l"(b), "l"(c));
    return d;
}
__device__ __forceinline__ void red_add_v4(float* p, float4 v) {
    asm volatile("red.global.add.v4.f32 [%0], {%1,%2,%3,%4};"
                 :: "l"(p), "f"(v.x), "f"(v.y), "f"(v.z), "f"(v.w) : "memory");
}
__device__ __forceinline__ float silu(float x) {
    return __fdividef(x, 1.0f + __expf(-x));
}

#define WSTR 132
#define HQS  20

// ============================================================================
// Kernel 1: hA/hB split across CTA parity.  78KB smem -> 2 CTAs/SM.
// 256 threads: tc = tid&127 output col, nh = tid>>7 node half.
// 32 nodes per pass (16 per half) to keep 8 accumulators per thread.
// ============================================================================
#define HAB_SMEM_FLOATS (128 * WSTR + HID * 36)
__global__ void __launch_bounds__(256, 2)
hab_kernel(const float* __restrict__ h,
           const float* __restrict__ e_w1,
           float* __restrict__ hA, float* __restrict__ hB) {
    extern __shared__ float s[];
    float* wT = s;                 // 128*132 [t][k]
    float* hq = wT + 128 * WSTR;   // 128*36  [k][m], 32 nodes + pad
    const int tid = threadIdx.x;
    const int tc = tid & 127;
    const int nh = tid >> 7;       // node half: m 0..15 or 16..31
    const int half = blockIdx.x & 1;

    for (int i = tid; i < HID * HID; i += 256) {
        const int tt = i & 127, kk = i >> 7;
        wT[tt * WSTR + kk] = e_w1[(kk + half * HID) * HID + tt];
    }
    __syncthreads();

    float* dst = half ? hB : hA;
    const int ngroups = N_NODES / 32;  // 1562 full groups + tail of 16
    const int gstep = gridDim.x >> 1;
    for (int g = blockIdx.x >> 1; g <= ngroups; g += gstep) {
        const int nb = g * 32;
        const int nrem = N_NODES - nb;            // 32 normally; 16 on tail
        const int mcount = nrem < 32 ? nrem : 32;
        for (int idx = tid; idx < mcount * HID; idx += 256) {
            const float v = h[nb * HID + idx];
            const int m = idx >> 7, k = idx & 127;
            hq[k * 36 + m] = v;
        }
        __syncthreads();

        const int mbase = nh * 16;
        if (mbase < mcount) {
            ull a[8];
#pragma unroll
            for (int i = 0; i < 8; i++) a[i] = 0ull;
#pragma unroll 4
            for (int k = 0; k < HID; k += 4) {
                const float4 wv = *(const float4*)&wT[tc * WSTR + k];
#pragma unroll
                for (int j = 0; j < 4; j++) {
                    const float wj = j == 0 ? wv.x : j == 1 ? wv.y : j == 2 ? wv.z : wv.w;
                    const ull wp = dup2(wj);
                    const ulonglong2* hp = (const ulonglong2*)&hq[(k + j) * 36 + mbase];
                    const ulonglong2 q0 = hp[0], q1 = hp[1], q2 = hp[2], q3 = hp[3];
                    a[0] = fma2(q0.x, wp, a[0]); a[1] = fma2(q0.y, wp, a[1]);
                    a[2] = fma2(q1.x, wp, a[2]); a[3] = fma2(q1.y, wp, a[3]);
                    a[4] = fma2(q2.x, wp, a[4]); a[5] = fma2(q2.y, wp, a[5]);
                    a[6] = fma2(q3.x, wp, a[6]); a[7] = fma2(q3.y, wp, a[7]);
                }
            }
#pragma unroll
            for (int i = 0; i < 8; i++) {
                const float2 f = unpack2(a[i]);
                dst[(nb + mbase + 2 * i + 0) * HID + tc] = f.x;
                dst[(nb + mbase + 2 * i + 1) * HID + tc] = f.y;
            }
        }
        __syncthreads();
    }
}

// ============================================================================
// Kernel 2: edge MLP + scatter (R13 structure + gather prefetch above sync).
// ============================================================================
#define EG 64
#define ESTR 68
#define EDGE_SMEM_FLOATS (HID * HID + ANF * ESTR + HID * ESTR)
__global__ void __launch_bounds__(256, 2)
edge_kernel(const float* __restrict__ hA, const float* __restrict__ hB,
            const int* __restrict__ row_idx, const int* __restrict__ col_idx,
            const float* __restrict__ edge_attr,
            const float* __restrict__ e_w1,
            const float* __restrict__ e_b1,
            const float* __restrict__ e_w2,
            const float* __restrict__ e_b2,
            float* __restrict__ gsum, float* __restrict__ gcnt) {
    extern __shared__ float s[];
    float* w2s    = s;
    float* attr_t = w2s + HID * HID;
    float* ef1t   = attr_t + ANF * ESTR;
    const int tid = threadIdx.x;
    const int fg  = tid & 31;
    const int eslot = tid >> 5;
    const int myE = 8 * eslot;
    const float* w1c = e_w1 + 2 * HID * HID;

    for (int i = tid; i < HID * HID; i += 256) w2s[i] = e_w2[i];
    const float4 b1v = *(const float4*)&e_b1[4 * fg];
    const float4 b2v = *(const float4*)&e_b2[4 * fg];
    __syncthreads();

    const int ngroups = N_EDGES / EG;
    for (int g = blockIdx.x; g < ngroups; g += gridDim.x) {
        const int e0g = g * EG;
        int rowv[8], colv[8];
#pragma unroll
        for (int e = 0; e < 8; e++) {
            rowv[e] = row_idx[e0g + myE + e];
            colv[e] = col_idx[e0g + myE + e];
        }
        // PREFETCH gathers above the barrier
        float4 gAv[8], gBv[8];
#pragma unroll
        for (int e = 0; e < 8; e++) {
            gAv[e] = *(const float4*)&hA[rowv[e] * HID + 4 * fg];
            gBv[e] = *(const float4*)&hB[colv[e] * HID + 4 * fg];
        }
        for (int idx = tid; idx < EG * ANF; idx += 256) {
            const float v = edge_attr[e0g * ANF + idx];
            const int e = idx >> 5, k = idx & 31;
            attr_t[k * ESTR + e] = v;
        }
        __syncthreads();                                            // (a)

        if (tid < EG) atomicAdd(&gcnt[row_idx[e0g + tid]], 1.0f);

        ull accL[16];
#pragma unroll
        for (int e = 0; e < 8; e++) {
            accL[e]     = pack2(gAv[e].x + gBv[e].x + b1v.x, gAv[e].y + gBv[e].y + b1v.y);
            accL[8 + e] = pack2(gAv[e].z + gBv[e].z + b1v.z, gAv[e].w + gBv[e].w + b1v.w);
        }
#pragma unroll 4
        for (int k = 0; k < ANF; k++) {
            const float4 wv = __ldg((const float4*)&w1c[k * HID + 4 * fg]);
            const ull w01 = pack2(wv.x, wv.y);
            const ull w23 = pack2(wv.z, wv.w);
            const float4 a0 = *(const float4*)&attr_t[k * ESTR + myE];
            const float4 a1 = *(const float4*)&attr_t[k * ESTR + myE + 4];
            accL[0] = fma2(w01, dup2(a0.x), accL[0]); accL[8]  = fma2(w23, dup2(a0.x), accL[8]);
            accL[1] = fma2(w01, dup2(a0.y), accL[1]); accL[9]  = fma2(w23, dup2(a0.y), accL[9]);
            accL[2] = fma2(w01, dup2(a0.z), accL[2]); accL[10] = fma2(w23, dup2(a0.z), accL[10]);
            accL[3] = fma2(w01, dup2(a0.w), accL[3]); accL[11] = fma2(w23, dup2(a0.w), accL[11]);
            accL[4] = fma2(w01, dup2(a1.x), accL[4]); accL[12] = fma2(w23, dup2(a1.x), accL[12]);
            accL[5] = fma2(w01, dup2(a1.y), accL[5]); accL[13] = fma2(w23, dup2(a1.y), accL[13]);
            accL[6] = fma2(w01, dup2(a1.z), accL[6]); accL[14] = fma2(w23, dup2(a1.z), accL[14]);
            accL[7] = fma2(w01, dup2(a1.w), accL[7]); accL[15] = fma2(w23, dup2(a1.w), accL[15]);
        }
        {
            float sv[4][8];
#pragma unroll
            for (int e = 0; e < 8; e++) {
                const float2 f0 = unpack2(accL[e]);
                const float2 f1 = unpack2(accL[8 + e]);
                sv[0][e] = silu(f0.x);
                sv[1][e] = silu(f0.y);
                sv[2][e] = silu(f1.x);
                sv[3][e] = silu(f1.y);
            }
#pragma unroll
            for (int c = 0; c < 4; c++) {
                float* dst = &ef1t[(4 * fg + c) * ESTR + myE];
                *(float4*)dst       = make_float4(sv[c][0], sv[c][1], sv[c][2], sv[c][3]);
                *(float4*)(dst + 4) = make_float4(sv[c][4], sv[c][5], sv[c][6], sv[c][7]);
            }
        }
        __syncthreads();                                            // (b)

        ull acc[16];
#pragma unroll
        for (int e = 0; e < 8; e++) {
            acc[e]     = pack2(b2v.x, b2v.y);
            acc[8 + e] = pack2(b2v.z, b2v.w);
        }
#pragma unroll 8
        for (int k = 0; k < HID; k++) {
            const float4 wv = *(const float4*)&w2s[k * HID + 4 * fg];
            const ull w01 = pack2(wv.x, wv.y);
            const ull w23 = pack2(wv.z, wv.w);
            const float4 a0 = *(const float4*)&ef1t[k * ESTR + myE];
            const float4 a1 = *(const float4*)&ef1t[k * ESTR + myE + 4];
            acc[0] = fma2(w01, dup2(a0.x), acc[0]); acc[8]  = fma2(w23, dup2(a0.x), acc[8]);
            acc[1] = fma2(w01, dup2(a0.y), acc[1]); acc[9]  = fma2(w23, dup2(a0.y), acc[9]);
            acc[2] = fma2(w01, dup2(a0.z), acc[2]); acc[10] = fma2(w23, dup2(a0.z), acc[10]);
            acc[3] = fma2(w01, dup2(a0.w), acc[3]); acc[11] = fma2(w23, dup2(a0.w), acc[11]);
            acc[4] = fma2(w01, dup2(a1.x), acc[4]); acc[12] = fma2(w23, dup2(a1.x), acc[12]);
            acc[5] = fma2(w01, dup2(a1.y), acc[5]); acc[13] = fma2(w23, dup2(a1.y), acc[13]);
            acc[6] = fma2(w01, dup2(a1.z), acc[6]); acc[14] = fma2(w23, dup2(a1.z), acc[14]);
            acc[7] = fma2(w01, dup2(a1.w), acc[7]); acc[15] = fma2(w23, dup2(a1.w), acc[15]);
        }
#pragma unroll
        for (int e = 0; e < 8; e++) {
            const float2 f0 = unpack2(acc[e]);
            const float2 f1 = unpack2(acc[8 + e]);
            red_add_v4(&gsum[rowv[e] * HID + 4 * fg],
                       make_float4(silu(f0.x), silu(f0.y), silu(f1.x), silu(f1.y)));
        }
    }
}

// ============================================================================
// Kernel 3 (unchanged): scatter-mean + node MLPs + Gram-Schmidt.
// ============================================================================
#define HSTRIDE 129
#define NODE_SMEM_FLOATS (256 * WSTR + HID * HQS + 32 * HSTRIDE + 2 * 384 + 256 + 8 + 96)
__global__ void __launch_bounds__(256, 1)
node_kernel(const float* __restrict__ gsum, const float* __restrict__ gcnt,
            const float* __restrict__ v1_w1, const float* __restrict__ v1_b1,
            const float* __restrict__ v1_w2, const float* __restrict__ v1_b2,
            const float* __restrict__ v2_w1, const float* __restrict__ v2_b1,
            const float* __restrict__ v2_w2, const float* __restrict__ v2_b2,
            float* __restrict__ out) {
    extern __shared__ float s[];
    float* wT   = s;
    float* nq   = wT + 256 * WSTR;
    float* hid  = nq + HID * HQS;
    float* w2a  = hid + 32 * HSTRIDE;
    float* w2b  = w2a + 384;
    float* sb   = w2b + 384;
    float* b2ab = sb + 256;
    float* vecs = b2ab + 8;
    const int tid = threadIdx.x;
    const int tl = tid & 127;

    for (int i = tid; i < HID * HID; i += 256) {
        const int tt = i & 127, kk = i >> 7;
        wT[tt * WSTR + kk] = v1_w1[kk * HID + tt];
        wT[(HID + tt) * WSTR + kk] = v2_w1[kk * HID + tt];
    }
    for (int i = tid; i < 384; i += 256) { w2a[i] = v1_w2[i]; w2b[i] = v2_w2[i]; }
    if (tid < 128) { sb[tid] = v1_b1[tid]; sb[tid + 128] = v2_b1[tid]; }
    if (tid < 3)   { b2ab[tid] = v1_b2[tid]; b2ab[4 + tid] = v2_b2[tid]; }
    __syncthreads();

    const float myb = sb[tid];
    const int ngroups = N_NODES / 16;
    for (int g = blockIdx.x; g < ngroups; g += gridDim.x) {
        const int nb = g * 16;
        for (int idx = tid; idx < 16 * HID; idx += 256) {
            const int m = idx >> 7, k = idx & 127;
            const float v = gsum[nb * HID + idx] / fmaxf(gcnt[nb + m], 1.0f);
            nq[k * HQS + m] = v;
        }
        __syncthreads();

        ull a[8];
#pragma unroll
        for (int i = 0; i < 8; i++) a[i] = dup2(myb);
#pragma unroll 4
        for (int k = 0; k < HID; k += 4) {
            const float4 wv = *(const float4*)&wT[tid * WSTR + k];
#pragma unroll
            for (int j = 0; j < 4; j++) {
                const float wj = j == 0 ? wv.x : j == 1 ? wv.y : j == 2 ? wv.z : wv.w;
                const ull wp = dup2(wj);
                const ulonglong2* hp = (const ulonglong2*)&nq[(k + j) * HQS];
                const ulonglong2 q0 = hp[0], q1 = hp[1], q2 = hp[2], q3 = hp[3];
                a[0] = fma2(q0.x, wp, a[0]); a[1] = fma2(q0.y, wp, a[1]);
                a[2] = fma2(q1.x, wp, a[2]); a[3] = fma2(q1.y, wp, a[3]);
                a[4] = fma2(q2.x, wp, a[4]); a[5] = fma2(q2.y, wp, a[5]);
                a[6] = fma2(q3.x, wp, a[6]); a[7] = fma2(q3.y, wp, a[7]);
            }
        }
        {
            const int br = tid >> 7;
#pragma unroll
            for (int i = 0; i < 8; i++) {
                const float2 f = unpack2(a[i]);
                hid[((2 * i + 0) * 2 + br) * HSTRIDE + tl] = silu(f.x);
                hid[((2 * i + 1) * 2 + br) * HSTRIDE + tl] = silu(f.y);
            }
        }
        __syncthreads();

        if (tid < 96) {
            const int m = tid / 6, r = tid % 6, br = r / 3, j = r % 3;
            const float* hh = &hid[(m * 2 + br) * HSTRIDE];
            const float* ww = br ? w2b : w2a;
            float acc = b2ab[br * 4 + j];
#pragma unroll 8
            for (int tt = 0; tt < HID; tt++) acc += hh[tt] * ww[tt * 3 + j];
            vecs[m * 6 + r] = acc;
        }
        __syncthreads();

        if (tid < 16) {
            const float* v = &vecs[tid * 6];
            float v1x = v[0], v1y = v[1], v1z = v[2];
            float v2x = v[3], v2y = v[4], v2z = v[5];
            float n1 = fmaxf(sqrtf(v1x * v1x + v1y * v1y + v1z * v1z), EPSV);
            v1x /= n1; v1y /= n1; v1z /= n1;
            const float d = v2x * v1x + v2y * v1y + v2z * v1z;
            v2x -= d * v1x; v2y -= d * v1y; v2z -= d * v1z;
            float n2 = fmaxf(sqrtf(v2x * v2x + v2y * v2y + v2z * v2z), EPSV);
            v2x /= n2; v2y /= n2; v2z /= n2;
            const float cx = v1y * v2z - v1z * v2y;
            const float cy = v1z * v2x - v1x * v2z;
            const float cz = v1x * v2y - v1y * v2x;
            float* o = &out[(size_t)(nb + tid) * 9];
            o[0] = v1x; o[1] = v2x; o[2] = cx;
            o[3] = v1y; o[4] = v2y; o[5] = cy;
            o[6] = v1z; o[7] = v2z; o[8] = cz;
        }
        __syncthreads();
    }
}

extern "C" void kernel_launch(void* const* d_in, const int* in_sizes, int n_in,
                              void* d_out, int out_size) {
    const float* h      = (const float*)d_in[0];
    const int*   eidx   = (const int*)d_in[2];
    const float* eattr  = (const float*)d_in[3];
    const float* e_w1   = (const float*)d_in[4];
    const float* e_b1   = (const float*)d_in[5];
    const float* e_w2   = (const float*)d_in[6];
    const float* e_b2   = (const float*)d_in[7];
    const float* v1_w1  = (const float*)d_in[8];
    const float* v1_b1  = (const float*)d_in[9];
    const float* v1_w2  = (const float*)d_in[10];
    const float* v1_b2  = (const float*)d_in[11];
    const float* v2_w1  = (const float*)d_in[12];
    const float* v2_b1  = (const float*)d_in[13];
    const float* v2_w2  = (const float*)d_in[14];
    const float* v2_b2  = (const float*)d_in[15];
    float* out = (float*)d_out;

    float *hA, *hB, *sum, *cnt;
    cudaGetSymbolAddress((void**)&hA, g_hA);
    cudaGetSymbolAddress((void**)&hB, g_hB);
    cudaGetSymbolAddress((void**)&sum, g_sum);
    cudaGetSymbolAddress((void**)&cnt, g_cnt);

    const int hab_smem  = HAB_SMEM_FLOATS * 4;
    const int edge_smem = EDGE_SMEM_FLOATS * 4;
    const int node_smem = NODE_SMEM_FLOATS * 4;
    cudaFuncSetAttribute(hab_kernel, cudaFuncAttributeMaxDynamicSharedMemorySize, hab_smem);
    cudaFuncSetAttribute(edge_kernel, cudaFuncAttributeMaxDynamicSharedMemorySize, edge_smem);
    cudaFuncSetAttribute(node_kernel, cudaFuncAttributeMaxDynamicSharedMemorySize, node_smem);

    cudaMemsetAsync(sum, 0, (size_t)N_NODES * HID * sizeof(float));
    cudaMemsetAsync(cnt, 0, (size_t)N_NODES * sizeof(float));

    hab_kernel<<<296, 256, hab_smem>>>(h, e_w1, hA, hB);
    edge_kernel<<<296, 256, edge_smem>>>(hA, hB, eidx, eidx + N_EDGES, eattr,
                                         e_w1, e_b1, e_w2, e_b2, sum, cnt);
    node_kernel<<<148, 256, node_smem>>>(sum, cnt,
                                         v1_w1, v1_b1, v1_w2, v1_b2,
                                         v2_w1, v2_b1, v2_w2, v2_b2, out);
}

// round 15
// speedup vs baseline: 1.0529x; 1.0529x over previous
#include <cuda_runtime.h>
#include <math.h>

#define N_NODES 50000
#define N_EDGES 800000
#define HID 128
#define ANF 32
#define EPSV 1e-12f

typedef unsigned long long ull;

__device__ float g_hA[N_NODES * HID];
__device__ float g_hB[N_NODES * HID];
__device__ float g_sum[N_NODES * HID];
__device__ float g_cnt[N_NODES];

__device__ __forceinline__ ull pack2(float x, float y) {
    ull r;
    asm("mov.b64 %0,{%1,%2};" : "=l"(r) : "r"(__float_as_uint(x)), "r"(__float_as_uint(y)));
    return r;
}
__device__ __forceinline__ ull dup2(float x) {
    ull r;
    asm("mov.b64 %0,{%1,%1};" : "=l"(r) : "r"(__float_as_uint(x)));
    return r;
}
__device__ __forceinline__ float2 unpack2(ull v) {
    unsigned a, b;
    asm("mov.b64 {%0,%1},%2;" : "=r"(a), "=r"(b) : "l"(v));
    return make_float2(__uint_as_float(a), __uint_as_float(b));
}
__device__ __forceinline__ ull fma2(ull a, ull b, ull c) {
    ull d;
    asm("fma.rn.f32x2 %0,%1,%2,%3;" : "=l"(d) : "l"(a), "l"(b), "l"(c));
    return d;
}
__device__ __forceinline__ void red_add_v4(float* p, float4 v) {
    asm volatile("red.global.add.v4.f32 [%0], {%1,%2,%3,%4};"
                 :: "l"(p), "f"(v.x), "f"(v.y), "f"(v.z), "f"(v.w) : "memory");
}
__device__ __forceinline__ float silu(float x) {
    return __fdividef(x, 1.0f + __expf(-x));
}

#define WSTR 132
#define HQS  20

// ============================================================================
// Kernel 1 (R14 measured-best): hA/hB split across CTA parity, 2 CTAs/SM.
// 256 threads: tc = tid&127 col, nh = tid>>7 node half, 32 nodes/pass.
// ============================================================================
#define HAB_SMEM_FLOATS (128 * WSTR + HID * 36)
__global__ void __launch_bounds__(256, 2)
hab_kernel(const float* __restrict__ h,
           const float* __restrict__ e_w1,
           float* __restrict__ hA, float* __restrict__ hB) {
    extern __shared__ float s[];
    float* wT = s;                 // 128*132 [t][k]
    float* hq = wT + 128 * WSTR;   // 128*36  [k][m]
    const int tid = threadIdx.x;
    const int tc = tid & 127;
    const int nh = tid >> 7;
    const int half = blockIdx.x & 1;

    for (int i = tid; i < HID * HID; i += 256) {
        const int tt = i & 127, kk = i >> 7;
        wT[tt * WSTR + kk] = e_w1[(kk + half * HID) * HID + tt];
    }
    __syncthreads();

    float* dst = half ? hB : hA;
    const int ngroups = N_NODES / 32;  // 1562 + tail 16
    const int gstep = gridDim.x >> 1;
    for (int g = blockIdx.x >> 1; g <= ngroups; g += gstep) {
        const int nb = g * 32;
        const int nrem = N_NODES - nb;
        const int mcount = nrem < 32 ? nrem : 32;
        for (int idx = tid; idx < mcount * HID; idx += 256) {
            const float v = h[nb * HID + idx];
            const int m = idx >> 7, k = idx & 127;
            hq[k * 36 + m] = v;
        }
        __syncthreads();

        const int mbase = nh * 16;
        if (mbase < mcount) {
            ull a[8];
#pragma unroll
            for (int i = 0; i < 8; i++) a[i] = 0ull;
#pragma unroll 4
            for (int k = 0; k < HID; k += 4) {
                const float4 wv = *(const float4*)&wT[tc * WSTR + k];
#pragma unroll
                for (int j = 0; j < 4; j++) {
                    const float wj = j == 0 ? wv.x : j == 1 ? wv.y : j == 2 ? wv.z : wv.w;
                    const ull wp = dup2(wj);
                    const ulonglong2* hp = (const ulonglong2*)&hq[(k + j) * 36 + mbase];
                    const ulonglong2 q0 = hp[0], q1 = hp[1], q2 = hp[2], q3 = hp[3];
                    a[0] = fma2(q0.x, wp, a[0]); a[1] = fma2(q0.y, wp, a[1]);
                    a[2] = fma2(q1.x, wp, a[2]); a[3] = fma2(q1.y, wp, a[3]);
                    a[4] = fma2(q2.x, wp, a[4]); a[5] = fma2(q2.y, wp, a[5]);
                    a[6] = fma2(q3.x, wp, a[6]); a[7] = fma2(q3.y, wp, a[7]);
                }
            }
#pragma unroll
            for (int i = 0; i < 8; i++) {
                const float2 f = unpack2(a[i]);
                dst[(nb + mbase + 2 * i + 0) * HID + tc] = f.x;
                dst[(nb + mbase + 2 * i + 1) * HID + tc] = f.y;
            }
        }
        __syncthreads();
    }
}

// ============================================================================
// Kernel 2: edge MLP + scatter.  256 threads, 2 CTAs/SM, 64 edges/group.
// fg = tid&31 (features 4fg..+3), eslot = tid>>5 (edges 8*eslot..+7).
// R15: accumulators laid out [feature][edge-pair] so the f32x2 PAIR operand
// is two adjacent edges straight out of the act LDS.128 (zero MOVs); only
// the 4 weights are dup'd (4 MOVs/k vs 10).  No gather prefetch (R14 lesson).
// ============================================================================
#define EG 64
#define ESTR 68
#define EDGE_SMEM_FLOATS (HID * HID + ANF * ESTR + HID * ESTR)
__global__ void __launch_bounds__(256, 2)
edge_kernel(const float* __restrict__ hA, const float* __restrict__ hB,
            const int* __restrict__ row_idx, const int* __restrict__ col_idx,
            const float* __restrict__ edge_attr,
            const float* __restrict__ e_w1,
            const float* __restrict__ e_b1,
            const float* __restrict__ e_w2,
            const float* __restrict__ e_b2,
            float* __restrict__ gsum, float* __restrict__ gcnt) {
    extern __shared__ float s[];
    float* w2s    = s;                    // 128*128 [k][f]
    float* attr_t = w2s + HID * HID;      // 32*68   [k][e]
    float* ef1t   = attr_t + ANF * ESTR;  // 128*68  [k][e]
    const int tid = threadIdx.x;
    const int fg  = tid & 31;
    const int eslot = tid >> 5;
    const int myE = 8 * eslot;
    const float* w1c = e_w1 + 2 * HID * HID;

    for (int i = tid; i < HID * HID; i += 256) w2s[i] = e_w2[i];
    const float4 b1v = *(const float4*)&e_b1[4 * fg];
    const float4 b2v = *(const float4*)&e_b2[4 * fg];
    __syncthreads();

    const int ngroups = N_EDGES / EG;  // 12500
    for (int g = blockIdx.x; g < ngroups; g += gridDim.x) {
        const int e0g = g * EG;
        int rowv[8], colv[8];
#pragma unroll
        for (int e = 0; e < 8; e++) {
            rowv[e] = row_idx[e0g + myE + e];
            colv[e] = col_idx[e0g + myE + e];
        }
        for (int idx = tid; idx < EG * ANF; idx += 256) {
            const float v = edge_attr[e0g * ANF + idx];
            const int e = idx >> 5, k = idx & 31;
            attr_t[k * ESTR + e] = v;
        }
        __syncthreads();                                            // (a)

        if (tid < EG) atomicAdd(&gcnt[row_idx[e0g + tid]], 1.0f);

        // -------- layer 1 --------
        // accL[c*4+p]: feature 4fg+c, edge pair (2p, 2p+1)
        ull accL[16];
        {
            float4 gA[8], gB[8];
#pragma unroll
            for (int e = 0; e < 8; e++) {
                gA[e] = *(const float4*)&hA[rowv[e] * HID + 4 * fg];
                gB[e] = *(const float4*)&hB[colv[e] * HID + 4 * fg];
            }
#pragma unroll
            for (int p = 0; p < 4; p++) {
                const float4 A0 = gA[2 * p], A1 = gA[2 * p + 1];
                const float4 B0 = gB[2 * p], B1 = gB[2 * p + 1];
                accL[0 * 4 + p] = pack2(A0.x + B0.x + b1v.x, A1.x + B1.x + b1v.x);
                accL[1 * 4 + p] = pack2(A0.y + B0.y + b1v.y, A1.y + B1.y + b1v.y);
                accL[2 * 4 + p] = pack2(A0.z + B0.z + b1v.z, A1.z + B1.z + b1v.z);
                accL[3 * 4 + p] = pack2(A0.w + B0.w + b1v.w, A1.w + B1.w + b1v.w);
            }
        }
#pragma unroll 4
        for (int k = 0; k < ANF; k++) {
            const float4 wv = __ldg((const float4*)&w1c[k * HID + 4 * fg]);
            const ull wd0 = dup2(wv.x), wd1 = dup2(wv.y);
            const ull wd2 = dup2(wv.z), wd3 = dup2(wv.w);
            float4 av[2];
            av[0] = *(const float4*)&attr_t[k * ESTR + myE];
            av[1] = *(const float4*)&attr_t[k * ESTR + myE + 4];
            const ull* ap = (const ull*)av;  // 4 edge-pairs, zero MOVs
#pragma unroll
            for (int p = 0; p < 4; p++) {
                accL[0 * 4 + p] = fma2(ap[p], wd0, accL[0 * 4 + p]);
                accL[1 * 4 + p] = fma2(ap[p], wd1, accL[1 * 4 + p]);
                accL[2 * 4 + p] = fma2(ap[p], wd2, accL[2 * 4 + p]);
                accL[3 * 4 + p] = fma2(ap[p], wd3, accL[3 * 4 + p]);
            }
        }
        {
            // silu + store rows 4fg+c, cols myE..myE+7
#pragma unroll
            for (int c = 0; c < 4; c++) {
                float sv[8];
#pragma unroll
                for (int p = 0; p < 4; p++) {
                    const float2 f = unpack2(accL[c * 4 + p]);
                    sv[2 * p]     = silu(f.x);
                    sv[2 * p + 1] = silu(f.y);
                }
                float* dst = &ef1t[(4 * fg + c) * ESTR + myE];
                *(float4*)dst       = make_float4(sv[0], sv[1], sv[2], sv[3]);
                *(float4*)(dst + 4) = make_float4(sv[4], sv[5], sv[6], sv[7]);
            }
        }
        __syncthreads();                                            // (b)

        // -------- layer 2 --------
        ull acc[16];
        {
            const ull i0 = dup2(b2v.x), i1 = dup2(b2v.y);
            const ull i2 = dup2(b2v.z), i3 = dup2(b2v.w);
#pragma unroll
            for (int p = 0; p < 4; p++) {
                acc[0 * 4 + p] = i0;
                acc[1 * 4 + p] = i1;
                acc[2 * 4 + p] = i2;
                acc[3 * 4 + p] = i3;
            }
        }
#pragma unroll 8
        for (int k = 0; k < HID; k++) {
            const float4 wv = *(const float4*)&w2s[k * HID + 4 * fg];
            const ull wd0 = dup2(wv.x), wd1 = dup2(wv.y);
            const ull wd2 = dup2(wv.z), wd3 = dup2(wv.w);
            float4 av[2];
            av[0] = *(const float4*)&ef1t[k * ESTR + myE];
            av[1] = *(const float4*)&ef1t[k * ESTR + myE + 4];
            const ull* ap = (const ull*)av;
#pragma unroll
            for (int p = 0; p < 4; p++) {
                acc[0 * 4 + p] = fma2(ap[p], wd0, acc[0 * 4 + p]);
                acc[1 * 4 + p] = fma2(ap[p], wd1, acc[1 * 4 + p]);
                acc[2 * 4 + p] = fma2(ap[p], wd2, acc[2 * 4 + p]);
                acc[3 * 4 + p] = fma2(ap[p], wd3, acc[3 * 4 + p]);
            }
        }
        // epilogue: per-edge silu + red.v4
#pragma unroll
        for (int p = 0; p < 4; p++) {
            const float2 f0 = unpack2(acc[0 * 4 + p]);
            const float2 f1 = unpack2(acc[1 * 4 + p]);
            const float2 f2 = unpack2(acc[2 * 4 + p]);
            const float2 f3 = unpack2(acc[3 * 4 + p]);
            red_add_v4(&gsum[rowv[2 * p] * HID + 4 * fg],
                       make_float4(silu(f0.x), silu(f1.x), silu(f2.x), silu(f3.x)));
            red_add_v4(&gsum[rowv[2 * p + 1] * HID + 4 * fg],
                       make_float4(silu(f0.y), silu(f1.y), silu(f2.y), silu(f3.y)));
        }
    }
}

// ============================================================================
// Kernel 3 (unchanged): scatter-mean + node MLPs + Gram-Schmidt.
// ============================================================================
#define HSTRIDE 129
#define NODE_SMEM_FLOATS (256 * WSTR + HID * HQS + 32 * HSTRIDE + 2 * 384 + 256 + 8 + 96)
__global__ void __launch_bounds__(256, 1)
node_kernel(const float* __restrict__ gsum, const float* __restrict__ gcnt,
            const float* __restrict__ v1_w1, const float* __restrict__ v1_b1,
            const float* __restrict__ v1_w2, const float* __restrict__ v1_b2,
            const float* __restrict__ v2_w1, const float* __restrict__ v2_b1,
            const float* __restrict__ v2_w2, const float* __restrict__ v2_b2,
            float* __restrict__ out) {
    extern __shared__ float s[];
    float* wT   = s;
    float* nq   = wT + 256 * WSTR;
    float* hid  = nq + HID * HQS;
    float* w2a  = hid + 32 * HSTRIDE;
    float* w2b  = w2a + 384;
    float* sb   = w2b + 384;
    float* b2ab = sb + 256;
    float* vecs = b2ab + 8;
    const int tid = threadIdx.x;
    const int tl = tid & 127;

    for (int i = tid; i < HID * HID; i += 256) {
        const int tt = i & 127, kk = i >> 7;
        wT[tt * WSTR + kk] = v1_w1[kk * HID + tt];
        wT[(HID + tt) * WSTR + kk] = v2_w1[kk * HID + tt];
    }
    for (int i = tid; i < 384; i += 256) { w2a[i] = v1_w2[i]; w2b[i] = v2_w2[i]; }
    if (tid < 128) { sb[tid] = v1_b1[tid]; sb[tid + 128] = v2_b1[tid]; }
    if (tid < 3)   { b2ab[tid] = v1_b2[tid]; b2ab[4 + tid] = v2_b2[tid]; }
    __syncthreads();

    const float myb = sb[tid];
    const int ngroups = N_NODES / 16;
    for (int g = blockIdx.x; g < ngroups; g += gridDim.x) {
        const int nb = g * 16;
        for (int idx = tid; idx < 16 * HID; idx += 256) {
            const int m = idx >> 7, k = idx & 127;
            const float v = gsum[nb * HID + idx] / fmaxf(gcnt[nb + m], 1.0f);
            nq[k * HQS + m] = v;
        }
        __syncthreads();

        ull a[8];
#pragma unroll
        for (int i = 0; i < 8; i++) a[i] = dup2(myb);
#pragma unroll 4
        for (int k = 0; k < HID; k += 4) {
            const float4 wv = *(const float4*)&wT[tid * WSTR + k];
#pragma unroll
            for (int j = 0; j < 4; j++) {
                const float wj = j == 0 ? wv.x : j == 1 ? wv.y : j == 2 ? wv.z : wv.w;
                const ull wp = dup2(wj);
                const ulonglong2* hp = (const ulonglong2*)&nq[(k + j) * HQS];
                const ulonglong2 q0 = hp[0], q1 = hp[1], q2 = hp[2], q3 = hp[3];
                a[0] = fma2(q0.x, wp, a[0]); a[1] = fma2(q0.y, wp, a[1]);
                a[2] = fma2(q1.x, wp, a[2]); a[3] = fma2(q1.y, wp, a[3]);
                a[4] = fma2(q2.x, wp, a[4]); a[5] = fma2(q2.y, wp, a[5]);
                a[6] = fma2(q3.x, wp, a[6]); a[7] = fma2(q3.y, wp, a[7]);
            }
        }
        {
            const int br = tid >> 7;
#pragma unroll
            for (int i = 0; i < 8; i++) {
                const float2 f = unpack2(a[i]);
                hid[((2 * i + 0) * 2 + br) * HSTRIDE + tl] = silu(f.x);
                hid[((2 * i + 1) * 2 + br) * HSTRIDE + tl] = silu(f.y);
            }
        }
        __syncthreads();

        if (tid < 96) {
            const int m = tid / 6, r = tid % 6, br = r / 3, j = r % 3;
            const float* hh = &hid[(m * 2 + br) * HSTRIDE];
            const float* ww = br ? w2b : w2a;
            float acc = b2ab[br * 4 + j];
#pragma unroll 8
            for (int tt = 0; tt < HID; tt++) acc += hh[tt] * ww[tt * 3 + j];
            vecs[m * 6 + r] = acc;
        }
        __syncthreads();

        if (tid < 16) {
            const float* v = &vecs[tid * 6];
            float v1x = v[0], v1y = v[1], v1z = v[2];
            float v2x = v[3], v2y = v[4], v2z = v[5];
            float n1 = fmaxf(sqrtf(v1x * v1x + v1y * v1y + v1z * v1z), EPSV);
            v1x /= n1; v1y /= n1; v1z /= n1;
            const float d = v2x * v1x + v2y * v1y + v2z * v1z;
            v2x -= d * v1x; v2y -= d * v1y; v2z -= d * v1z;
            float n2 = fmaxf(sqrtf(v2x * v2x + v2y * v2y + v2z * v2z), EPSV);
            v2x /= n2; v2y /= n2; v2z /= n2;
            const float cx = v1y * v2z - v1z * v2y;
            const float cy = v1z * v2x - v1x * v2z;
            const float cz = v1x * v2y - v1y * v2x;
            float* o = &out[(size_t)(nb + tid) * 9];
            o[0] = v1x; o[1] = v2x; o[2] = cx;
            o[3] = v1y; o[4] = v2y; o[5] = cy;
            o[6] = v1z; o[7] = v2z; o[8] = cz;
        }
        __syncthreads();
    }
}

extern "C" void kernel_launch(void* const* d_in, const int* in_sizes, int n_in,
                              void* d_out, int out_size) {
    const float* h      = (const float*)d_in[0];
    const int*   eidx   = (const int*)d_in[2];
    const float* eattr  = (const float*)d_in[3];
    const float* e_w1   = (const float*)d_in[4];
    const float* e_b1   = (const float*)d_in[5];
    const float* e_w2   = (const float*)d_in[6];
    const float* e_b2   = (const float*)d_in[7];
    const float* v1_w1  = (const float*)d_in[8];
    const float* v1_b1  = (const float*)d_in[9];
    const float* v1_w2  = (const float*)d_in[10];
    const float* v1_b2  = (const float*)d_in[11];
    const float* v2_w1  = (const float*)d_in[12];
    const float* v2_b1  = (const float*)d_in[13];
    const float* v2_w2  = (const float*)d_in[14];
    const float* v2_b2  = (const float*)d_in[15];
    float* out = (float*)d_out;

    float *hA, *hB, *sum, *cnt;
    cudaGetSymbolAddress((void**)&hA, g_hA);
    cudaGetSymbolAddress((void**)&hB, g_hB);
    cudaGetSymbolAddress((void**)&sum, g_sum);
    cudaGetSymbolAddress((void**)&cnt, g_cnt);

    const int hab_smem  = HAB_SMEM_FLOATS * 4;
    const int edge_smem = EDGE_SMEM_FLOATS * 4;
    const int node_smem = NODE_SMEM_FLOATS * 4;
    cudaFuncSetAttribute(hab_kernel, cudaFuncAttributeMaxDynamicSharedMemorySize, hab_smem);
    cudaFuncSetAttribute(edge_kernel, cudaFuncAttributeMaxDynamicSharedMemorySize, edge_smem);
    cudaFuncSetAttribute(node_kernel, cudaFuncAttributeMaxDynamicSharedMemorySize, node_smem);

    cudaMemsetAsync(sum, 0, (size_t)N_NODES * HID * sizeof(float));
    cudaMemsetAsync(cnt, 0, (size_t)N_NODES * sizeof(float));

    hab_kernel<<<296, 256, hab_smem>>>(h, e_w1, hA, hB);
    edge_kernel<<<296, 256, edge_smem>>>(hA, hB, eidx, eidx + N_EDGES, eattr,
                                         e_w1, e_b1, e_w2, e_b2, sum, cnt);
    node_kernel<<<148, 256, node_smem>>>(sum, cnt,
                                         v1_w1, v1_b1, v1_w2, v1_b2,
                                         v2_w1, v2_b1, v2_w2, v2_b2, out);
}

// round 16
// speedup vs baseline: 1.1002x; 1.0448x over previous
#include <cuda_runtime.h>
#include <math.h>

#define N_NODES 50000
#define N_EDGES 800000
#define HID 128
#define ANF 32
#define EPSV 1e-12f

typedef unsigned long long ull;

__device__ float g_hA[N_NODES * HID];
__device__ float g_hB[N_NODES * HID];
__device__ float g_sum[N_NODES * HID];
__device__ float g_cnt[N_NODES];

__device__ __forceinline__ ull pack2(float x, float y) {
    ull r;
    asm("mov.b64 %0,{%1,%2};" : "=l"(r) : "r"(__float_as_uint(x)), "r"(__float_as_uint(y)));
    return r;
}
__device__ __forceinline__ ull dup2(float x) {
    ull r;
    asm("mov.b64 %0,{%1,%1};" : "=l"(r) : "r"(__float_as_uint(x)));
    return r;
}
__device__ __forceinline__ float2 unpack2(ull v) {
    unsigned a, b;
    asm("mov.b64 {%0,%1},%2;" : "=r"(a), "=r"(b) : "l"(v));
    return make_float2(__uint_as_float(a), __uint_as_float(b));
}
__device__ __forceinline__ ull fma2(ull a, ull b, ull c) {
    ull d;
    asm("fma.rn.f32x2 %0,%1,%2,%3;" : "=l"(d) : "l"(a), "l"(b), "l"(c));
    return d;
}
__device__ __forceinline__ void red_add_v4(float* p, float4 v) {
    asm volatile("red.global.add.v4.f32 [%0], {%1,%2,%3,%4};"
                 :: "l"(p), "f"(v.x), "f"(v.y), "f"(v.z), "f"(v.w) : "memory");
}
__device__ __forceinline__ float silu(float x) {
    return __fdividef(x, 1.0f + __expf(-x));
}

#define WSTR 132
#define HQS  20

// ============================================================================
// Kernel 1 (R14/R15 measured-best): hA/hB split across CTA parity, 2 CTAs/SM.
// ============================================================================
#define HAB_SMEM_FLOATS (128 * WSTR + HID * 36)
__global__ void __launch_bounds__(256, 2)
hab_kernel(const float* __restrict__ h,
           const float* __restrict__ e_w1,
           float* __restrict__ hA, float* __restrict__ hB) {
    extern __shared__ float s[];
    float* wT = s;                 // 128*132 [t][k]
    float* hq = wT + 128 * WSTR;   // 128*36  [k][m]
    const int tid = threadIdx.x;
    const int tc = tid & 127;
    const int nh = tid >> 7;
    const int half = blockIdx.x & 1;

    for (int i = tid; i < HID * HID; i += 256) {
        const int tt = i & 127, kk = i >> 7;
        wT[tt * WSTR + kk] = e_w1[(kk + half * HID) * HID + tt];
    }
    __syncthreads();

    float* dst = half ? hB : hA;
    const int ngroups = N_NODES / 32;  // 1562 + tail 16
    const int gstep = gridDim.x >> 1;
    for (int g = blockIdx.x >> 1; g <= ngroups; g += gstep) {
        const int nb = g * 32;
        const int nrem = N_NODES - nb;
        const int mcount = nrem < 32 ? nrem : 32;
        for (int idx = tid; idx < mcount * HID; idx += 256) {
            const float v = h[nb * HID + idx];
            const int m = idx >> 7, k = idx & 127;
            hq[k * 36 + m] = v;
        }
        __syncthreads();

        const int mbase = nh * 16;
        if (mbase < mcount) {
            ull a[8];
#pragma unroll
            for (int i = 0; i < 8; i++) a[i] = 0ull;
#pragma unroll 4
            for (int k = 0; k < HID; k += 4) {
                const float4 wv = *(const float4*)&wT[tc * WSTR + k];
#pragma unroll
                for (int j = 0; j < 4; j++) {
                    const float wj = j == 0 ? wv.x : j == 1 ? wv.y : j == 2 ? wv.z : wv.w;
                    const ull wp = dup2(wj);
                    const ulonglong2* hp = (const ulonglong2*)&hq[(k + j) * 36 + mbase];
                    const ulonglong2 q0 = hp[0], q1 = hp[1], q2 = hp[2], q3 = hp[3];
                    a[0] = fma2(q0.x, wp, a[0]); a[1] = fma2(q0.y, wp, a[1]);
                    a[2] = fma2(q1.x, wp, a[2]); a[3] = fma2(q1.y, wp, a[3]);
                    a[4] = fma2(q2.x, wp, a[4]); a[5] = fma2(q2.y, wp, a[5]);
                    a[6] = fma2(q3.x, wp, a[6]); a[7] = fma2(q3.y, wp, a[7]);
                }
            }
#pragma unroll
            for (int i = 0; i < 8; i++) {
                const float2 f = unpack2(a[i]);
                dst[(nb + mbase + 2 * i + 0) * HID + tc] = f.x;
                dst[(nb + mbase + 2 * i + 1) * HID + tc] = f.y;
            }
        }
        __syncthreads();
    }
}

// ============================================================================
// Kernel 2: edge MLP + scatter — WARP-AUTONOMOUS groups (R16).
// Each warp independently processes 8-edge groups (no block syncs in loop):
//   fg = lane (features 4fg..4fg+3); warp's smem slices: attr/ef1 cols myE.
// Layer-1 computes ALL 128 features of the warp's 8 edges inside the warp,
// so the ef1 exchange is intra-warp -> __syncwarp() suffices.
// Accumulators [feature][edge-pair] (R15): act pairs direct from LDS.128.
// ============================================================================
#define ESTR 68
#define EDGE_SMEM_FLOATS (HID * HID + ANF * ESTR + HID * ESTR)
__global__ void __launch_bounds__(256, 2)
edge_kernel(const float* __restrict__ hA, const float* __restrict__ hB,
            const int* __restrict__ row_idx, const int* __restrict__ col_idx,
            const float* __restrict__ edge_attr,
            const float* __restrict__ e_w1,
            const float* __restrict__ e_b1,
            const float* __restrict__ e_w2,
            const float* __restrict__ e_b2,
            float* __restrict__ gsum, float* __restrict__ gcnt) {
    extern __shared__ float s[];
    float* w2s    = s;                    // 128*128 [k][f] (shared, read-only)
    float* attr_t = w2s + HID * HID;      // 32*68   [k][e] (per-warp col slice)
    float* ef1t   = attr_t + ANF * ESTR;  // 128*68  [k][e] (per-warp col slice)
    const int tid = threadIdx.x;
    const int fg  = tid & 31;
    const int wslot = tid >> 5;   // warp in block (0..7)
    const int myE = 8 * wslot;
    const float* w1c = e_w1 + 2 * HID * HID;

    for (int i = tid; i < HID * HID; i += 256) w2s[i] = e_w2[i];
    const float4 b1v = *(const float4*)&e_b1[4 * fg];
    const float4 b2v = *(const float4*)&e_b2[4 * fg];
    __syncthreads();  // only block sync: w2s ready

    const int nwg = N_EDGES / 8;            // 100000 warp-groups
    const int wg0 = blockIdx.x * 8 + wslot;
    const int wstride = gridDim.x * 8;      // total warps
    for (int wg = wg0; wg < nwg; wg += wstride) {
        const int e0 = wg * 8;
        int rowv[8], colv[8];
#pragma unroll
        for (int e = 0; e < 8; e++) {
            rowv[e] = row_idx[e0 + e];
            colv[e] = col_idx[e0 + e];
        }
        // per-warp attr staging: warp reads its contiguous 1KB, transposed STS
#pragma unroll
        for (int i = 0; i < 8; i++) {
            const int idx = fg * 8 + i;          // 0..255
            const float v = edge_attr[e0 * ANF + idx];
            const int e = idx >> 5, k = idx & 31;
            attr_t[k * ESTR + myE + e] = v;
        }
        __syncwarp();                                          // (a) intra-warp

        if (fg < 8) atomicAdd(&gcnt[rowv[fg]], 1.0f);

        // -------- layer 1 --------
        // accL[c*4+p]: feature 4fg+c, edge pair (2p, 2p+1)
        ull accL[16];
        {
            float4 gA[8], gB[8];
#pragma unroll
            for (int e = 0; e < 8; e++) {
                gA[e] = *(const float4*)&hA[rowv[e] * HID + 4 * fg];
                gB[e] = *(const float4*)&hB[colv[e] * HID + 4 * fg];
            }
#pragma unroll
            for (int p = 0; p < 4; p++) {
                const float4 A0 = gA[2 * p], A1 = gA[2 * p + 1];
                const float4 B0 = gB[2 * p], B1 = gB[2 * p + 1];
                accL[0 * 4 + p] = pack2(A0.x + B0.x + b1v.x, A1.x + B1.x + b1v.x);
                accL[1 * 4 + p] = pack2(A0.y + B0.y + b1v.y, A1.y + B1.y + b1v.y);
                accL[2 * 4 + p] = pack2(A0.z + B0.z + b1v.z, A1.z + B1.z + b1v.z);
                accL[3 * 4 + p] = pack2(A0.w + B0.w + b1v.w, A1.w + B1.w + b1v.w);
            }
        }
#pragma unroll 4
        for (int k = 0; k < ANF; k++) {
            const float4 wv = __ldg((const float4*)&w1c[k * HID + 4 * fg]);
            const ull wd0 = dup2(wv.x), wd1 = dup2(wv.y);
            const ull wd2 = dup2(wv.z), wd3 = dup2(wv.w);
            float4 av[2];
            av[0] = *(const float4*)&attr_t[k * ESTR + myE];
            av[1] = *(const float4*)&attr_t[k * ESTR + myE + 4];
            const ull* ap = (const ull*)av;
#pragma unroll
            for (int p = 0; p < 4; p++) {
                accL[0 * 4 + p] = fma2(ap[p], wd0, accL[0 * 4 + p]);
                accL[1 * 4 + p] = fma2(ap[p], wd1, accL[1 * 4 + p]);
                accL[2 * 4 + p] = fma2(ap[p], wd2, accL[2 * 4 + p]);
                accL[3 * 4 + p] = fma2(ap[p], wd3, accL[3 * 4 + p]);
            }
        }
        {
#pragma unroll
            for (int c = 0; c < 4; c++) {
                float sv[8];
#pragma unroll
                for (int p = 0; p < 4; p++) {
                    const float2 f = unpack2(accL[c * 4 + p]);
                    sv[2 * p]     = silu(f.x);
                    sv[2 * p + 1] = silu(f.y);
                }
                float* dst = &ef1t[(4 * fg + c) * ESTR + myE];
                *(float4*)dst       = make_float4(sv[0], sv[1], sv[2], sv[3]);
                *(float4*)(dst + 4) = make_float4(sv[4], sv[5], sv[6], sv[7]);
            }
        }
        __syncwarp();                                          // (b) intra-warp

        // -------- layer 2 --------
        ull acc[16];
        {
            const ull i0 = dup2(b2v.x), i1 = dup2(b2v.y);
            const ull i2 = dup2(b2v.z), i3 = dup2(b2v.w);
#pragma unroll
            for (int p = 0; p < 4; p++) {
                acc[0 * 4 + p] = i0;
                acc[1 * 4 + p] = i1;
                acc[2 * 4 + p] = i2;
                acc[3 * 4 + p] = i3;
            }
        }
#pragma unroll 8
        for (int k = 0; k < HID; k++) {
            const float4 wv = *(const float4*)&w2s[k * HID + 4 * fg];
            const ull wd0 = dup2(wv.x), wd1 = dup2(wv.y);
            const ull wd2 = dup2(wv.z), wd3 = dup2(wv.w);
            float4 av[2];
            av[0] = *(const float4*)&ef1t[k * ESTR + myE];
            av[1] = *(const float4*)&ef1t[k * ESTR + myE + 4];
            const ull* ap = (const ull*)av;
#pragma unroll
            for (int p = 0; p < 4; p++) {
                acc[0 * 4 + p] = fma2(ap[p], wd0, acc[0 * 4 + p]);
                acc[1 * 4 + p] = fma2(ap[p], wd1, acc[1 * 4 + p]);
                acc[2 * 4 + p] = fma2(ap[p], wd2, acc[2 * 4 + p]);
                acc[3 * 4 + p] = fma2(ap[p], wd3, acc[3 * 4 + p]);
            }
        }
        // epilogue: per-edge silu + red.v4
#pragma unroll
        for (int p = 0; p < 4; p++) {
            const float2 f0 = unpack2(acc[0 * 4 + p]);
            const float2 f1 = unpack2(acc[1 * 4 + p]);
            const float2 f2 = unpack2(acc[2 * 4 + p]);
            const float2 f3 = unpack2(acc[3 * 4 + p]);
            red_add_v4(&gsum[rowv[2 * p] * HID + 4 * fg],
                       make_float4(silu(f0.x), silu(f1.x), silu(f2.x), silu(f3.x)));
            red_add_v4(&gsum[rowv[2 * p + 1] * HID + 4 * fg],
                       make_float4(silu(f0.y), silu(f1.y), silu(f2.y), silu(f3.y)));
        }
        // next iter's attr/ef1 writes ordered vs this iter's reads by (a)/(b)
    }
}

// ============================================================================
// Kernel 3 (unchanged): scatter-mean + node MLPs + Gram-Schmidt.
// ============================================================================
#define HSTRIDE 129
#define NODE_SMEM_FLOATS (256 * WSTR + HID * HQS + 32 * HSTRIDE + 2 * 384 + 256 + 8 + 96)
__global__ void __launch_bounds__(256, 1)
node_kernel(const float* __restrict__ gsum, const float* __restrict__ gcnt,
            const float* __restrict__ v1_w1, const float* __restrict__ v1_b1,
            const float* __restrict__ v1_w2, const float* __restrict__ v1_b2,
            const float* __restrict__ v2_w1, const float* __restrict__ v2_b1,
            const float* __restrict__ v2_w2, const float* __restrict__ v2_b2,
            float* __restrict__ out) {
    extern __shared__ float s[];
    float* wT   = s;
    float* nq   = wT + 256 * WSTR;
    float* hid  = nq + HID * HQS;
    float* w2a  = hid + 32 * HSTRIDE;
    float* w2b  = w2a + 384;
    float* sb   = w2b + 384;
    float* b2ab = sb + 256;
    float* vecs = b2ab + 8;
    const int tid = threadIdx.x;
    const int tl = tid & 127;

    for (int i = tid; i < HID * HID; i += 256) {
        const int tt = i & 127, kk = i >> 7;
        wT[tt * WSTR + kk] = v1_w1[kk * HID + tt];
        wT[(HID + tt) * WSTR + kk] = v2_w1[kk * HID + tt];
    }
    for (int i = tid; i < 384; i += 256) { w2a[i] = v1_w2[i]; w2b[i] = v2_w2[i]; }
    if (tid < 128) { sb[tid] = v1_b1[tid]; sb[tid + 128] = v2_b1[tid]; }
    if (tid < 3)   { b2ab[tid] = v1_b2[tid]; b2ab[4 + tid] = v2_b2[tid]; }
    __syncthreads();

    const float myb = sb[tid];
    const int ngroups = N_NODES / 16;
    for (int g = blockIdx.x; g < ngroups; g += gridDim.x) {
        const int nb = g * 16;
        for (int idx = tid; idx < 16 * HID; idx += 256) {
            const int m = idx >> 7, k = idx & 127;
            const float v = gsum[nb * HID + idx] / fmaxf(gcnt[nb + m], 1.0f);
            nq[k * HQS + m] = v;
        }
        __syncthreads();

        ull a[8];
#pragma unroll
        for (int i = 0; i < 8; i++) a[i] = dup2(myb);
#pragma unroll 4
        for (int k = 0; k < HID; k += 4) {
            const float4 wv = *(const float4*)&wT[tid * WSTR + k];
#pragma unroll
            for (int j = 0; j < 4; j++) {
                const float wj = j == 0 ? wv.x : j == 1 ? wv.y : j == 2 ? wv.z : wv.w;
                const ull wp = dup2(wj);
                const ulonglong2* hp = (const ulonglong2*)&nq[(k + j) * HQS];
                const ulonglong2 q0 = hp[0], q1 = hp[1], q2 = hp[2], q3 = hp[3];
                a[0] = fma2(q0.x, wp, a[0]); a[1] = fma2(q0.y, wp, a[1]);
                a[2] = fma2(q1.x, wp, a[2]); a[3] = fma2(q1.y, wp, a[3]);
                a[4] = fma2(q2.x, wp, a[4]); a[5] = fma2(q2.y, wp, a[5]);
                a[6] = fma2(q3.x, wp, a[6]); a[7] = fma2(q3.y, wp, a[7]);
            }
        }
        {
            const int br = tid >> 7;
#pragma unroll
            for (int i = 0; i < 8; i++) {
                const float2 f = unpack2(a[i]);
                hid[((2 * i + 0) * 2 + br) * HSTRIDE + tl] = silu(f.x);
                hid[((2 * i + 1) * 2 + br) * HSTRIDE + tl] = silu(f.y);
            }
        }
        __syncthreads();

        if (tid < 96) {
            const int m = tid / 6, r = tid % 6, br = r / 3, j = r % 3;
            const float* hh = &hid[(m * 2 + br) * HSTRIDE];
            const float* ww = br ? w2b : w2a;
            float acc = b2ab[br * 4 + j];
#pragma unroll 8
            for (int tt = 0; tt < HID; tt++) acc += hh[tt] * ww[tt * 3 + j];
            vecs[m * 6 + r] = acc;
        }
        __syncthreads();

        if (tid < 16) {
            const float* v = &vecs[tid * 6];
            float v1x = v[0], v1y = v[1], v1z = v[2];
            float v2x = v[3], v2y = v[4], v2z = v[5];
            float n1 = fmaxf(sqrtf(v1x * v1x + v1y * v1y + v1z * v1z), EPSV);
            v1x /= n1; v1y /= n1; v1z /= n1;
            const float d = v2x * v1x + v2y * v1y + v2z * v1z;
            v2x -= d * v1x; v2y -= d * v1y; v2z -= d * v1z;
            float n2 = fmaxf(sqrtf(v2x * v2x + v2y * v2y + v2z * v2z), EPSV);
            v2x /= n2; v2y /= n2; v2z /= n2;
            const float cx = v1y * v2z - v1z * v2y;
            const float cy = v1z * v2x - v1x * v2z;
            const float cz = v1x * v2y - v1y * v2x;
            float* o = &out[(size_t)(nb + tid) * 9];
            o[0] = v1x; o[1] = v2x; o[2] = cx;
            o[3] = v1y; o[4] = v2y; o[5] = cy;
            o[6] = v1z; o[7] = v2z; o[8] = cz;
        }
        __syncthreads();
    }
}

extern "C" void kernel_launch(void* const* d_in, const int* in_sizes, int n_in,
                              void* d_out, int out_size) {
    const float* h      = (const float*)d_in[0];
    const int*   eidx   = (const int*)d_in[2];
    const float* eattr  = (const float*)d_in[3];
    const float* e_w1   = (const float*)d_in[4];
    const float* e_b1   = (const float*)d_in[5];
    const float* e_w2   = (const float*)d_in[6];
    const float* e_b2   = (const float*)d_in[7];
    const float* v1_w1  = (const float*)d_in[8];
    const float* v1_b1  = (const float*)d_in[9];
    const float* v1_w2  = (const float*)d_in[10];
    const float* v1_b2  = (const float*)d_in[11];
    const float* v2_w1  = (const float*)d_in[12];
    const float* v2_b1  = (const float*)d_in[13];
    const float* v2_w2  = (const float*)d_in[14];
    const float* v2_b2  = (const float*)d_in[15];
    float* out = (float*)d_out;

    float *hA, *hB, *sum, *cnt;
    cudaGetSymbolAddress((void**)&hA, g_hA);
    cudaGetSymbolAddress((void**)&hB, g_hB);
    cudaGetSymbolAddress((void**)&sum, g_sum);
    cudaGetSymbolAddress((void**)&cnt, g_cnt);

    const int hab_smem  = HAB_SMEM_FLOATS * 4;
    const int edge_smem = EDGE_SMEM_FLOATS * 4;
    const int node_smem = NODE_SMEM_FLOATS * 4;
    cudaFuncSetAttribute(hab_kernel, cudaFuncAttributeMaxDynamicSharedMemorySize, hab_smem);
    cudaFuncSetAttribute(edge_kernel, cudaFuncAttributeMaxDynamicSharedMemorySize, edge_smem);
    cudaFuncSetAttribute(node_kernel, cudaFuncAttributeMaxDynamicSharedMemorySize, node_smem);

    cudaMemsetAsync(sum, 0, (size_t)N_NODES * HID * sizeof(float));
    cudaMemsetAsync(cnt, 0, (size_t)N_NODES * sizeof(float));

    hab_kernel<<<296, 256, hab_smem>>>(h, e_w1, hA, hB);
    edge_kernel<<<296, 256, edge_smem>>>(hA, hB, eidx, eidx + N_EDGES, eattr,
                                         e_w1, e_b1, e_w2, e_b2, sum, cnt);
    node_kernel<<<148, 256, node_smem>>>(sum, cnt,
                                         v1_w1, v1_b1, v1_w2, v1_b2,
                                         v2_w1, v2_b1, v2_w2, v2_b2, out);
}